// round 14
// baseline (speedup 1.0000x reference)
#include <cuda_runtime.h>
#include <cuda_fp16.h>
#include <math.h>
#include <stdint.h>

#define BATCH 4
#define SEQ   2048
#define DMODEL 1024
#define NH    16
#define DH    64

// Scratch (device globals; allocation-free per harness rules)
__device__ __half g_X   [BATCH * SEQ * DMODEL];   // x, fp16
__device__ __half g_Wqkv[DMODEL * 3 * DMODEL];    // [k][ Wq | Wk | Wv ] fp16
__device__ __half g_Wo  [DMODEL * DMODEL];        // Wo fp16, natural [k][n]
__device__ __half g_Q   [BATCH * NH * SEQ * DH];  // [b,h,l,d]
__device__ __half g_K   [BATCH * NH * SEQ * DH];
__device__ __half g_V   [BATCH * NH * SEQ * DH];
__device__ __half g_ctx [BATCH * SEQ * DMODEL];   // [b,l,h*64+d]

// ---------------------------------------------------------------------------
// helpers
// ---------------------------------------------------------------------------
__device__ __forceinline__ uint32_t smem_u32(const void* p) {
    uint32_t a;
    asm("{ .reg .u64 t; cvta.to.shared.u64 t, %1; cvt.u32.u64 %0, t; }"
        : "=r"(a) : "l"(p));
    return a;
}

__device__ __forceinline__ void mma_f16(float* c,
    uint32_t a0, uint32_t a1, uint32_t a2, uint32_t a3,
    uint32_t b0, uint32_t b1)
{
    asm("mma.sync.aligned.m16n8k16.row.col.f32.f16.f16.f32 "
        "{%0,%1,%2,%3}, {%4,%5,%6,%7}, {%8,%9}, {%0,%1,%2,%3};"
        : "+f"(c[0]), "+f"(c[1]), "+f"(c[2]), "+f"(c[3])
        : "r"(a0), "r"(a1), "r"(a2), "r"(a3), "r"(b0), "r"(b1));
}

__device__ __forceinline__ void ldsm4(uint32_t* r, uint32_t a) {
    asm volatile("ldmatrix.sync.aligned.m8n8.x4.shared.b16 {%0,%1,%2,%3}, [%4];"
        : "=r"(r[0]), "=r"(r[1]), "=r"(r[2]), "=r"(r[3]) : "r"(a));
}
__device__ __forceinline__ void ldsm4t(uint32_t* r, uint32_t a) {
    asm volatile("ldmatrix.sync.aligned.m8n8.x4.trans.shared.b16 {%0,%1,%2,%3}, [%4];"
        : "=r"(r[0]), "=r"(r[1]), "=r"(r[2]), "=r"(r[3]) : "r"(a));
}

__device__ __forceinline__ uint32_t packh2(float a, float b) {
    __half2 h = __floats2half2_rn(a, b);
    return *reinterpret_cast<uint32_t*>(&h);
}

__device__ __forceinline__ void cpa16(uint32_t dst, const void* src) {
    asm volatile("cp.async.cg.shared.global [%0], [%1], 16;"
                 :: "r"(dst), "l"(src) : "memory");
}
#define CP_COMMIT() asm volatile("cp.async.commit_group;" ::: "memory")
#define CP_WAIT(n)  asm volatile("cp.async.wait_group %0;" :: "n"(n) : "memory")

// ---------------------------------------------------------------------------
// Pre-pass (single kernel): x -> fp16, fused QKV weight pack, Wo -> fp16
// ---------------------------------------------------------------------------
#define NX4  (BATCH * SEQ * DMODEL / 4)          // 2097152
#define NQKV (DMODEL * 768)                      // 786432
#define NWO  (DMODEL * DMODEL / 4)               // 262144

__global__ __launch_bounds__(256)
void conv_all_kernel(const float4* __restrict__ x,
                     const float4* __restrict__ wq, const float4* __restrict__ wk,
                     const float4* __restrict__ wv, const float4* __restrict__ wo)
{
    const int idx = blockIdx.x * 256 + threadIdx.x;
    const float4* src;
    uint2* dst;
    if (idx < NX4) {
        src = x + idx;
        dst = (uint2*)g_X + idx;
    } else if (idx < NX4 + NQKV) {
        const int j = idx - NX4;
        const int k = j / 768;
        const int c4 = j - k * 768;
        const int mat = c4 >> 8;
        const int n4 = c4 & 255;
        src = ((mat == 0) ? wq : (mat == 1) ? wk : wv) + k * 256 + n4;
        dst = (uint2*)g_Wqkv + j;
    } else if (idx < NX4 + NQKV + NWO) {
        const int j = idx - NX4 - NQKV;
        src = wo + j;
        dst = (uint2*)g_Wo + j;
    } else {
        return;
    }
    float4 v = *src;
    uint2 o;
    o.x = packh2(v.x, v.y);
    o.y = packh2(v.z, v.w);
    *dst = o;
}

// ---------------------------------------------------------------------------
// fp16 GEMM: out[8192, N] = A @ W + bias       (W natural [k][n], ldw = N)
// Block tile 128x128, 128 threads (4 warps, 2x2), warp tile 64x64, K-tile 64,
// 3-stage cp.async pipeline, 2 CTAs/SM. 16 mainloop iterations (half the
// barriers of K-tile 32). A rows 144 B pitch, W k-rows 272 B pitch
// (pitch = 4 banks mod 32 -> conflict-free LDSM / LDSM.trans).
// SPLIT: fused QKV (N=3072), scatter to [b,h,l,d] fp16; else N=1024 fp32 out.
// ---------------------------------------------------------------------------
#define GA_BUF 18432             // 128 rows * 144 B
#define GB_BUF 17408             // 64 rows * 272 B
#define GB_BASE (3 * GA_BUF)     // 55296
#define GEMM_SMEM (3 * (GA_BUF + GB_BUF))   // 107520

__device__ __forceinline__ void gemm_stage(
    uint32_t sb, const __half* __restrict__ A, const __half* __restrict__ W,
    int ldw, int bm, int bn, int kt, int tid)
{
    const int k0 = kt * 64;
    const int buf = kt % 3;
    const uint32_t ab = sb + buf * GA_BUF;
    const uint32_t bb = sb + GB_BASE + buf * GB_BUF;
    #pragma unroll
    for (int i = 0; i < 8; i++) {
        const int p = tid + i * 128;               // 0..1023
        // A: row = p>>3 (128 rows), 16B slot = p&7 (64 k-halves)
        cpa16(ab + (p >> 3) * 144 + (p & 7) * 16,
              A + (size_t)(bm + (p >> 3)) * 1024 + k0 + (p & 7) * 8);
        // B: k-row = p>>4 (64 rows), 16B slot = p&15 (128 cols)
        cpa16(bb + (p >> 4) * 272 + (p & 15) * 16,
              W + (size_t)(k0 + (p >> 4)) * ldw + bn + (p & 15) * 8);
    }
    CP_COMMIT();
}

template <bool SPLIT>
__global__ __launch_bounds__(128, 2)
void gemm_f16_kernel(const __half* __restrict__ A, const __half* __restrict__ W,
                     int ldw,
                     const float* __restrict__ b0, const float* __restrict__ b1,
                     const float* __restrict__ b2,
                     __half* __restrict__ oq, __half* __restrict__ ok,
                     __half* __restrict__ ov, float* __restrict__ of)
{
    extern __shared__ char smem[];
    const uint32_t sb = smem_u32(smem);
    const int tid = threadIdx.x, lane = tid & 31, wid = tid >> 5;
    const int warp_m = wid >> 1, warp_n = wid & 1;
    const int bm = blockIdx.y * 128, bn = blockIdx.x * 128;
    const int g = lane >> 2, l4 = lane & 3;
    const int sect = lane >> 3, li = lane & 7;

    const uint32_t aoff = (uint32_t)(warp_m * 64 + (sect & 1) * 8 + li) * 144
                        + (sect >> 1) * 16;
    const uint32_t boff = (uint32_t)((sect & 1) * 8 + li) * 272
                        + (sect >> 1) * 16 + warp_n * 128;

    float acc[4][8][4];
    #pragma unroll
    for (int mt = 0; mt < 4; mt++)
        #pragma unroll
        for (int nt = 0; nt < 8; nt++)
            #pragma unroll
            for (int i = 0; i < 4; i++) acc[mt][nt][i] = 0.f;

    gemm_stage(sb, A, W, ldw, bm, bn, 0, tid);
    gemm_stage(sb, A, W, ldw, bm, bn, 1, tid);

    for (int kt = 0; kt < 16; kt++) {
        if (kt >= 14) { CP_WAIT(0); } else { CP_WAIT(1); }
        __syncthreads();
        if (kt < 14) gemm_stage(sb, A, W, ldw, bm, bn, kt + 2, tid);

        const int buf = kt % 3;
        const uint32_t abase = sb + buf * GA_BUF + aoff;
        const uint32_t bbase = sb + GB_BASE + buf * GB_BUF + boff;

        #pragma unroll
        for (int ks = 0; ks < 4; ks++) {
            uint32_t af[4][4], bf[4][4];
            #pragma unroll
            for (int mt = 0; mt < 4; mt++)
                ldsm4(af[mt], abase + mt * 16 * 144 + ks * 32);
            #pragma unroll
            for (int t = 0; t < 4; t++)
                ldsm4t(bf[t], bbase + ks * 16 * 272 + t * 32);
            #pragma unroll
            for (int mt = 0; mt < 4; mt++)
                #pragma unroll
                for (int nt = 0; nt < 8; nt++)
                    mma_f16(acc[mt][nt],
                            af[mt][0], af[mt][1], af[mt][2], af[mt][3],
                            bf[nt >> 1][(nt & 1) * 2], bf[nt >> 1][(nt & 1) * 2 + 1]);
        }
    }

    // Epilogue. For SPLIT, the 128-wide n-block lies entirely inside one of
    // Q/K/V (128 | 1024), so the matrix select is uniform per block.
    __half* oh = oq;
    const float* bias = b0;
    if (SPLIT) {
        const int mat = bn >> 10;
        oh   = (mat == 0) ? oq : (mat == 1) ? ok : ov;
        bias = (mat == 0) ? b0 : (mat == 1) ? b1 : b2;
    }
    #pragma unroll
    for (int mt = 0; mt < 4; mt++) {
        const int r0 = bm + warp_m * 64 + mt * 16 + g;
        const int r1 = r0 + 8;
        #pragma unroll
        for (int nt = 0; nt < 8; nt++) {
            const int c  = bn + warp_n * 64 + nt * 8 + 2 * l4;
            const int cn = SPLIT ? (c & 1023) : c;
            const float bx = bias[cn], by = bias[cn + 1];
            const float v0x = acc[mt][nt][0] + bx, v0y = acc[mt][nt][1] + by;
            const float v1x = acc[mt][nt][2] + bx, v1y = acc[mt][nt][3] + by;
            if (SPLIT) {
                const int h = cn >> 6, d = cn & 63;
                const int b0_ = r0 >> 11, l0_ = r0 & 2047;
                const int b1_ = r1 >> 11, l1_ = r1 & 2047;
                *(uint32_t*)(oh + ((size_t)((b0_ * NH + h) * SEQ + l0_)) * DH + d) =
                    packh2(v0x, v0y);
                *(uint32_t*)(oh + ((size_t)((b1_ * NH + h) * SEQ + l1_)) * DH + d) =
                    packh2(v1x, v1y);
            } else {
                *(float2*)(of + (size_t)r0 * 1024 + c) = make_float2(v0x, v0y);
                *(float2*)(of + (size_t)r1 * 1024 + c) = make_float2(v1x, v1y);
            }
        }
    }
}

// ---------------------------------------------------------------------------
// Flash attention (causal), fp16 m16n8k16, P in registers.
// 256 threads (8 warps), q-tile 128 (16 rows/warp), kv-tile 64.
// K/V double-buffered via cp.async.
// ---------------------------------------------------------------------------
#define ATT_QB 0
#define ATT_KB 18432
#define ATT_VB 36864
#define ATT_SMEM 55296

__device__ __forceinline__ void attn_stage_kv(
    uint32_t sb, const __half* Kg, const __half* Vg, int jt, int tid)
{
    const int buf = jt & 1;
    const uint32_t kb = sb + ATT_KB + buf * 9216;
    const uint32_t vb = sb + ATT_VB + buf * 9216;
    #pragma unroll
    for (int i = 0; i < 2; i++) {
        const int p = tid + i * 256;
        const int row = p >> 3, c16 = p & 7;
        cpa16(kb + row * 144 + c16 * 16,
              Kg + (size_t)(jt * 64 + row) * 64 + c16 * 8);
        cpa16(vb + row * 144 + c16 * 16,
              Vg + (size_t)(jt * 64 + row) * 64 + c16 * 8);
    }
    CP_COMMIT();
}

__global__ __launch_bounds__(256, 2)
void attn_f16_kernel()
{
    extern __shared__ char smc[];
    const uint32_t sb = smem_u32(smc);

    const int tid  = threadIdx.x;
    const int lane = tid & 31;
    const int wid  = tid >> 5;
    const int g    = lane >> 2;
    const int l4   = lane & 3;
    const int sect = lane >> 3, li = lane & 7;
    const int qt   = gridDim.x - 1 - blockIdx.x;   // heavy blocks first
    const int bh   = blockIdx.y;
    const int m0   = wid * 16;

    const __half* Qg = g_Q + ((size_t)bh * SEQ + qt * 128) * DH;
    const __half* Kg = g_K + (size_t)bh * SEQ * DH;
    const __half* Vg = g_V + (size_t)bh * SEQ * DH;

    const uint32_t qaddr0 = sb + ATT_QB
        + (uint32_t)(m0 + (sect & 1) * 8 + li) * 144 + (sect >> 1) * 16;
    const uint32_t koff = (uint32_t)((sect >> 1) * 8 + li) * 144 + (sect & 1) * 16;
    const uint32_t voff = (uint32_t)((sect & 1) * 8 + li) * 144 + (sect >> 1) * 16;

    attn_stage_kv(sb, Kg, Vg, 0, tid);

    const __half2 scl = __half2half2(__float2half(0.125f));
    #pragma unroll
    for (int i = 0; i < 4; i++) {
        const int p = tid + i * 256;
        const int row = p >> 3, dc = (p & 7) * 8;
        uint4 v = *(const uint4*)(Qg + row * 64 + dc);
        __half2* h = (__half2*)&v;
        h[0] = __hmul2(h[0], scl); h[1] = __hmul2(h[1], scl);
        h[2] = __hmul2(h[2], scl); h[3] = __hmul2(h[3], scl);
        *(uint4*)(smc + ATT_QB + row * 144 + dc * 2) = v;
    }
    __syncthreads();

    uint32_t qa[4][4];
    #pragma unroll
    for (int ks = 0; ks < 4; ks++) ldsm4(qa[ks], qaddr0 + ks * 32);

    float o[8][4];
    #pragma unroll
    for (int nt = 0; nt < 8; nt++)
        #pragma unroll
        for (int i = 0; i < 4; i++) o[nt][i] = 0.f;
    float mrow[2] = {-1e30f, -1e30f};
    float lrow[2] = {0.f, 0.f};

    const int R0  = qt * 128 + m0;
    const int r0g = R0 + g;
    const int r1g = r0g + 8;
    const int ntiles = 2 * qt + 2;

    for (int jt = 0; jt < ntiles; jt++) {
        CP_WAIT(0);
        __syncthreads();
        if (jt + 1 < ntiles) attn_stage_kv(sb, Kg, Vg, jt + 1, tid);

        if (jt * 64 > R0 + 15) continue;

        const int buf = jt & 1;
        const uint32_t kaddr0 = sb + ATT_KB + buf * 9216 + koff;
        const uint32_t vaddr0 = sb + ATT_VB + buf * 9216 + voff;

        float s[8][4];
        #pragma unroll
        for (int nt = 0; nt < 8; nt++)
            #pragma unroll
            for (int i = 0; i < 4; i++) s[nt][i] = 0.f;

        #pragma unroll
        for (int t = 0; t < 4; t++) {
            #pragma unroll
            for (int ks = 0; ks < 4; ks++) {
                uint32_t kb[4];
                ldsm4(kb, kaddr0 + t * 16 * 144 + ks * 32);
                mma_f16(s[2 * t],     qa[ks][0], qa[ks][1], qa[ks][2], qa[ks][3],
                        kb[0], kb[1]);
                mma_f16(s[2 * t + 1], qa[ks][0], qa[ks][1], qa[ks][2], qa[ks][3],
                        kb[2], kb[3]);
            }
        }

        if (jt * 64 + 63 > R0) {
            #pragma unroll
            for (int nt = 0; nt < 8; nt++) {
                const int c = jt * 64 + nt * 8 + 2 * l4;
                if (c     > r0g) s[nt][0] = -1e30f;
                if (c + 1 > r0g) s[nt][1] = -1e30f;
                if (c     > r1g) s[nt][2] = -1e30f;
                if (c + 1 > r1g) s[nt][3] = -1e30f;
            }
        }

        float mx0 = -1e30f, mx1 = -1e30f;
        #pragma unroll
        for (int nt = 0; nt < 8; nt++) {
            mx0 = fmaxf(mx0, fmaxf(s[nt][0], s[nt][1]));
            mx1 = fmaxf(mx1, fmaxf(s[nt][2], s[nt][3]));
        }
        mx0 = fmaxf(mx0, __shfl_xor_sync(0xffffffffu, mx0, 1));
        mx0 = fmaxf(mx0, __shfl_xor_sync(0xffffffffu, mx0, 2));
        mx1 = fmaxf(mx1, __shfl_xor_sync(0xffffffffu, mx1, 1));
        mx1 = fmaxf(mx1, __shfl_xor_sync(0xffffffffu, mx1, 2));

        const float mn0 = fmaxf(mrow[0], mx0);
        const float mn1 = fmaxf(mrow[1], mx1);
        const float c0 = __expf(mrow[0] - mn0);
        const float c1 = __expf(mrow[1] - mn1);

        float sum0 = 0.f, sum1 = 0.f;
        #pragma unroll
        for (int nt = 0; nt < 8; nt++) {
            s[nt][0] = __expf(s[nt][0] - mn0);
            s[nt][1] = __expf(s[nt][1] - mn0);
            s[nt][2] = __expf(s[nt][2] - mn1);
            s[nt][3] = __expf(s[nt][3] - mn1);
            sum0 += s[nt][0] + s[nt][1];
            sum1 += s[nt][2] + s[nt][3];
        }
        sum0 += __shfl_xor_sync(0xffffffffu, sum0, 1);
        sum0 += __shfl_xor_sync(0xffffffffu, sum0, 2);
        sum1 += __shfl_xor_sync(0xffffffffu, sum1, 1);
        sum1 += __shfl_xor_sync(0xffffffffu, sum1, 2);

        lrow[0] = lrow[0] * c0 + sum0;
        lrow[1] = lrow[1] * c1 + sum1;
        mrow[0] = mn0;
        mrow[1] = mn1;
        #pragma unroll
        for (int nt = 0; nt < 8; nt++) {
            o[nt][0] *= c0; o[nt][1] *= c0;
            o[nt][2] *= c1; o[nt][3] *= c1;
        }

        uint32_t ph[4][4];
        #pragma unroll
        for (int ks = 0; ks < 4; ks++) {
            ph[ks][0] = packh2(s[2 * ks][0],     s[2 * ks][1]);
            ph[ks][1] = packh2(s[2 * ks][2],     s[2 * ks][3]);
            ph[ks][2] = packh2(s[2 * ks + 1][0], s[2 * ks + 1][1]);
            ph[ks][3] = packh2(s[2 * ks + 1][2], s[2 * ks + 1][3]);
        }

        #pragma unroll
        for (int t = 0; t < 4; t++) {
            #pragma unroll
            for (int ks = 0; ks < 4; ks++) {
                uint32_t vb[4];
                ldsm4t(vb, vaddr0 + ks * 16 * 144 + t * 32);
                mma_f16(o[2 * t],     ph[ks][0], ph[ks][1], ph[ks][2], ph[ks][3],
                        vb[0], vb[1]);
                mma_f16(o[2 * t + 1], ph[ks][0], ph[ks][1], ph[ks][2], ph[ks][3],
                        vb[2], vb[3]);
            }
        }
    }

    const int b_ = bh >> 4;
    const int h_ = bh & 15;
    const float inv0 = 1.f / lrow[0];
    const float inv1 = 1.f / lrow[1];
    __half* c0p = g_ctx + ((size_t)(b_ * SEQ + qt * 128 + m0 + g))     * DMODEL + h_ * 64;
    __half* c1p = g_ctx + ((size_t)(b_ * SEQ + qt * 128 + m0 + 8 + g)) * DMODEL + h_ * 64;
    #pragma unroll
    for (int nt = 0; nt < 8; nt++) {
        *(uint32_t*)(c0p + nt * 8 + 2 * l4) = packh2(o[nt][0] * inv0, o[nt][1] * inv0);
        *(uint32_t*)(c1p + nt * 8 + 2 * l4) = packh2(o[nt][2] * inv1, o[nt][3] * inv1);
    }
}

// ---------------------------------------------------------------------------
extern "C" void kernel_launch(void* const* d_in, const int* in_sizes, int n_in,
                              void* d_out, int out_size)
{
    const float* x  = (const float*)d_in[0];
    const float* Wq = (const float*)d_in[2];
    const float* bq = (const float*)d_in[3];
    const float* Wk = (const float*)d_in[4];
    const float* bk = (const float*)d_in[5];
    const float* Wv = (const float*)d_in[6];
    const float* bv = (const float*)d_in[7];
    const float* Wo = (const float*)d_in[8];
    const float* bo = (const float*)d_in[9];
    float* out = (float*)d_out;

    __half *qp, *kp, *vp, *cp, *xp, *wqkv, *wo;
    cudaGetSymbolAddress((void**)&xp,   g_X);
    cudaGetSymbolAddress((void**)&wqkv, g_Wqkv);
    cudaGetSymbolAddress((void**)&wo,   g_Wo);
    cudaGetSymbolAddress((void**)&qp,   g_Q);
    cudaGetSymbolAddress((void**)&kp,   g_K);
    cudaGetSymbolAddress((void**)&vp,   g_V);
    cudaGetSymbolAddress((void**)&cp,   g_ctx);

    // Pre-pass: one kernel converts/pack everything
    const int ntot = NX4 + NQKV + NWO;
    conv_all_kernel<<<(ntot + 255) / 256, 256>>>(
        (const float4*)x, (const float4*)Wq, (const float4*)Wk,
        (const float4*)Wv, (const float4*)Wo);

    cudaFuncSetAttribute(gemm_f16_kernel<true>,
                         cudaFuncAttributeMaxDynamicSharedMemorySize, GEMM_SMEM);
    cudaFuncSetAttribute(gemm_f16_kernel<false>,
                         cudaFuncAttributeMaxDynamicSharedMemorySize, GEMM_SMEM);

    // Fused QKV projection: one launch, N = 3072
    gemm_f16_kernel<true><<<dim3(24, 64), 128, GEMM_SMEM>>>(
        xp, wqkv, 3 * DMODEL, bq, bk, bv, qp, kp, vp, nullptr);

    cudaFuncSetAttribute(attn_f16_kernel,
                         cudaFuncAttributeMaxDynamicSharedMemorySize, ATT_SMEM);
    attn_f16_kernel<<<dim3(16, 64), 256, ATT_SMEM>>>();

    // Output projection: N = 1024, fp32 out
    gemm_f16_kernel<false><<<dim3(8, 64), 128, GEMM_SMEM>>>(
        cp, wo, DMODEL, bo, nullptr, nullptr, nullptr, nullptr, nullptr, out);
}

// round 15
// speedup vs baseline: 1.0816x; 1.0816x over previous
#include <cuda_runtime.h>
#include <cuda_fp16.h>
#include <math.h>
#include <stdint.h>

#define BATCH 4
#define SEQ   2048
#define DMODEL 1024
#define NH    16
#define DH    64

// Scratch (device globals; allocation-free per harness rules)
__device__ __half g_X   [BATCH * SEQ * DMODEL];   // x, fp16
__device__ __half g_Wqkv[DMODEL * 3 * DMODEL];    // [k][ Wq | Wk | Wv ] fp16
__device__ __half g_Wo  [DMODEL * DMODEL];        // Wo fp16, natural [k][n]
__device__ __half g_Q   [BATCH * NH * SEQ * DH];  // [b,h,l,d]
__device__ __half g_K   [BATCH * NH * SEQ * DH];
__device__ __half g_V   [BATCH * NH * SEQ * DH];
__device__ __half g_ctx [BATCH * SEQ * DMODEL];   // [b,l,h*64+d]

// ---------------------------------------------------------------------------
// helpers
// ---------------------------------------------------------------------------
__device__ __forceinline__ uint32_t smem_u32(const void* p) {
    uint32_t a;
    asm("{ .reg .u64 t; cvta.to.shared.u64 t, %1; cvt.u32.u64 %0, t; }"
        : "=r"(a) : "l"(p));
    return a;
}

__device__ __forceinline__ void mma_f16(float* c,
    uint32_t a0, uint32_t a1, uint32_t a2, uint32_t a3,
    uint32_t b0, uint32_t b1)
{
    asm("mma.sync.aligned.m16n8k16.row.col.f32.f16.f16.f32 "
        "{%0,%1,%2,%3}, {%4,%5,%6,%7}, {%8,%9}, {%0,%1,%2,%3};"
        : "+f"(c[0]), "+f"(c[1]), "+f"(c[2]), "+f"(c[3])
        : "r"(a0), "r"(a1), "r"(a2), "r"(a3), "r"(b0), "r"(b1));
}

__device__ __forceinline__ void ldsm4(uint32_t* r, uint32_t a) {
    asm volatile("ldmatrix.sync.aligned.m8n8.x4.shared.b16 {%0,%1,%2,%3}, [%4];"
        : "=r"(r[0]), "=r"(r[1]), "=r"(r[2]), "=r"(r[3]) : "r"(a));
}
__device__ __forceinline__ void ldsm4t(uint32_t* r, uint32_t a) {
    asm volatile("ldmatrix.sync.aligned.m8n8.x4.trans.shared.b16 {%0,%1,%2,%3}, [%4];"
        : "=r"(r[0]), "=r"(r[1]), "=r"(r[2]), "=r"(r[3]) : "r"(a));
}

__device__ __forceinline__ uint32_t packh2(float a, float b) {
    __half2 h = __floats2half2_rn(a, b);
    return *reinterpret_cast<uint32_t*>(&h);
}

__device__ __forceinline__ void cpa16(uint32_t dst, const void* src) {
    asm volatile("cp.async.cg.shared.global [%0], [%1], 16;"
                 :: "r"(dst), "l"(src) : "memory");
}
#define CP_COMMIT() asm volatile("cp.async.commit_group;" ::: "memory")
#define CP_WAIT(n)  asm volatile("cp.async.wait_group %0;" :: "n"(n) : "memory")

// ---------------------------------------------------------------------------
// Pre-pass (single kernel): x -> fp16, fused QKV weight pack, Wo -> fp16
// ---------------------------------------------------------------------------
#define NX4  (BATCH * SEQ * DMODEL / 4)          // 2097152
#define NQKV (DMODEL * 768)                      // 786432
#define NWO  (DMODEL * DMODEL / 4)               // 262144

__global__ __launch_bounds__(256)
void conv_all_kernel(const float4* __restrict__ x,
                     const float4* __restrict__ wq, const float4* __restrict__ wk,
                     const float4* __restrict__ wv, const float4* __restrict__ wo)
{
    const int idx = blockIdx.x * 256 + threadIdx.x;
    const float4* src;
    uint2* dst;
    if (idx < NX4) {
        src = x + idx;
        dst = (uint2*)g_X + idx;
    } else if (idx < NX4 + NQKV) {
        const int j = idx - NX4;
        const int k = j / 768;
        const int c4 = j - k * 768;
        const int mat = c4 >> 8;
        const int n4 = c4 & 255;
        src = ((mat == 0) ? wq : (mat == 1) ? wk : wv) + k * 256 + n4;
        dst = (uint2*)g_Wqkv + j;
    } else if (idx < NX4 + NQKV + NWO) {
        const int j = idx - NX4 - NQKV;
        src = wo + j;
        dst = (uint2*)g_Wo + j;
    } else {
        return;
    }
    float4 v = *src;
    uint2 o;
    o.x = packh2(v.x, v.y);
    o.y = packh2(v.z, v.w);
    *dst = o;
}

// ---------------------------------------------------------------------------
// fp16 GEMM: out[8192, N] = A @ W + bias       (W natural [k][n], ldw = N)
// Block tile 128x128, 128 threads (4 warps, 2x2), warp tile 64x64, K-tile 32,
// 3-stage cp.async pipeline, 2 CTAs/SM (proven R13 config).
// A rows 80 B pitch; W k-rows 272 B pitch (conflict-free LDSM / LDSM.trans).
// SPLIT: fused QKV (N=3072), scatter to [b,h,l,d] fp16; else N=1024 fp32 out.
// ---------------------------------------------------------------------------
#define GA_BUF 10240             // 128 * 80
#define GB_BUF 8704              // 32 * 272
#define GB_BASE (3 * GA_BUF)     // 30720
#define GEMM_SMEM (3 * GA_BUF + 3 * GB_BUF)   // 56832

__device__ __forceinline__ void gemm_stage(
    uint32_t sb, const __half* __restrict__ A, const __half* __restrict__ W,
    int ldw, int bm, int bn, int kt, int tid)
{
    const int k0 = kt * 32;
    const int buf = kt % 3;
    const uint32_t ab = sb + buf * GA_BUF;
    const uint32_t bb = sb + GB_BASE + buf * GB_BUF;
    #pragma unroll
    for (int i = 0; i < 4; i++) {
        const int p = tid + i * 128;               // 0..511
        cpa16(ab + (p >> 2) * 80 + (p & 3) * 16,
              A + (size_t)(bm + (p >> 2)) * 1024 + k0 + (p & 3) * 8);
        cpa16(bb + (p >> 4) * 272 + (p & 15) * 16,
              W + (size_t)(k0 + (p >> 4)) * ldw + bn + (p & 15) * 8);
    }
    CP_COMMIT();
}

template <bool SPLIT>
__global__ __launch_bounds__(128, 2)
void gemm_f16_kernel(const __half* __restrict__ A, const __half* __restrict__ W,
                     int ldw,
                     const float* __restrict__ b0, const float* __restrict__ b1,
                     const float* __restrict__ b2,
                     __half* __restrict__ oq, __half* __restrict__ ok,
                     __half* __restrict__ ov, float* __restrict__ of)
{
    extern __shared__ char smem[];
    const uint32_t sb = smem_u32(smem);
    const int tid = threadIdx.x, lane = tid & 31, wid = tid >> 5;
    const int warp_m = wid >> 1, warp_n = wid & 1;
    const int bm = blockIdx.y * 128, bn = blockIdx.x * 128;
    const int g = lane >> 2, l4 = lane & 3;
    const int sect = lane >> 3, li = lane & 7;

    const uint32_t aoff = (uint32_t)(warp_m * 64 + (sect & 1) * 8 + li) * 80
                        + (sect >> 1) * 16;
    const uint32_t boff = (uint32_t)((sect & 1) * 8 + li) * 272
                        + (sect >> 1) * 16 + warp_n * 128;

    float acc[4][8][4];
    #pragma unroll
    for (int mt = 0; mt < 4; mt++)
        #pragma unroll
        for (int nt = 0; nt < 8; nt++)
            #pragma unroll
            for (int i = 0; i < 4; i++) acc[mt][nt][i] = 0.f;

    gemm_stage(sb, A, W, ldw, bm, bn, 0, tid);
    gemm_stage(sb, A, W, ldw, bm, bn, 1, tid);

    for (int kt = 0; kt < 32; kt++) {
        if (kt >= 30) { CP_WAIT(0); } else { CP_WAIT(1); }
        __syncthreads();
        if (kt < 30) gemm_stage(sb, A, W, ldw, bm, bn, kt + 2, tid);

        const int buf = kt % 3;
        const uint32_t abase = sb + buf * GA_BUF + aoff;
        const uint32_t bbase = sb + GB_BASE + buf * GB_BUF + boff;

        #pragma unroll
        for (int ks = 0; ks < 2; ks++) {
            uint32_t af[4][4], bf[4][4];
            #pragma unroll
            for (int mt = 0; mt < 4; mt++)
                ldsm4(af[mt], abase + mt * 16 * 80 + ks * 32);
            #pragma unroll
            for (int t = 0; t < 4; t++)
                ldsm4t(bf[t], bbase + ks * 16 * 272 + t * 32);
            #pragma unroll
            for (int mt = 0; mt < 4; mt++)
                #pragma unroll
                for (int nt = 0; nt < 8; nt++)
                    mma_f16(acc[mt][nt],
                            af[mt][0], af[mt][1], af[mt][2], af[mt][3],
                            bf[nt >> 1][(nt & 1) * 2], bf[nt >> 1][(nt & 1) * 2 + 1]);
        }
    }

    // Epilogue. For SPLIT, the 128-wide n-block lies entirely inside one of
    // Q/K/V (128 | 1024), so the matrix select is uniform per block.
    __half* oh = oq;
    const float* bias = b0;
    if (SPLIT) {
        const int mat = bn >> 10;
        oh   = (mat == 0) ? oq : (mat == 1) ? ok : ov;
        bias = (mat == 0) ? b0 : (mat == 1) ? b1 : b2;
    }
    #pragma unroll
    for (int mt = 0; mt < 4; mt++) {
        const int r0 = bm + warp_m * 64 + mt * 16 + g;
        const int r1 = r0 + 8;
        #pragma unroll
        for (int nt = 0; nt < 8; nt++) {
            const int c  = bn + warp_n * 64 + nt * 8 + 2 * l4;
            const int cn = SPLIT ? (c & 1023) : c;
            const float bx = bias[cn], by = bias[cn + 1];
            const float v0x = acc[mt][nt][0] + bx, v0y = acc[mt][nt][1] + by;
            const float v1x = acc[mt][nt][2] + bx, v1y = acc[mt][nt][3] + by;
            if (SPLIT) {
                const int h = cn >> 6, d = cn & 63;
                const int b0_ = r0 >> 11, l0_ = r0 & 2047;
                const int b1_ = r1 >> 11, l1_ = r1 & 2047;
                *(uint32_t*)(oh + ((size_t)((b0_ * NH + h) * SEQ + l0_)) * DH + d) =
                    packh2(v0x, v0y);
                *(uint32_t*)(oh + ((size_t)((b1_ * NH + h) * SEQ + l1_)) * DH + d) =
                    packh2(v1x, v1y);
            } else {
                *(float2*)(of + (size_t)r0 * 1024 + c) = make_float2(v0x, v0y);
                *(float2*)(of + (size_t)r1 * 1024 + c) = make_float2(v1x, v1y);
            }
        }
    }
}

// ---------------------------------------------------------------------------
// Flash attention (causal), fp16 m16n8k16, P in registers.
// 256 threads (8 warps), q-tile 128 (16 rows/warp), kv-tile 64.
// K/V double-buffered via cp.async. Softmax in log2 domain:
// Q pre-scaled by 0.125*log2(e); all exponentials are bare exp2f (EX2).
// ---------------------------------------------------------------------------
#define ATT_QB 0
#define ATT_KB 18432
#define ATT_VB 36864
#define ATT_SMEM 55296

__device__ __forceinline__ void attn_stage_kv(
    uint32_t sb, const __half* Kg, const __half* Vg, int jt, int tid)
{
    const int buf = jt & 1;
    const uint32_t kb = sb + ATT_KB + buf * 9216;
    const uint32_t vb = sb + ATT_VB + buf * 9216;
    #pragma unroll
    for (int i = 0; i < 2; i++) {
        const int p = tid + i * 256;
        const int row = p >> 3, c16 = p & 7;
        cpa16(kb + row * 144 + c16 * 16,
              Kg + (size_t)(jt * 64 + row) * 64 + c16 * 8);
        cpa16(vb + row * 144 + c16 * 16,
              Vg + (size_t)(jt * 64 + row) * 64 + c16 * 8);
    }
    CP_COMMIT();
}

__global__ __launch_bounds__(256, 2)
void attn_f16_kernel()
{
    extern __shared__ char smc[];
    const uint32_t sb = smem_u32(smc);

    const int tid  = threadIdx.x;
    const int lane = tid & 31;
    const int wid  = tid >> 5;
    const int g    = lane >> 2;
    const int l4   = lane & 3;
    const int sect = lane >> 3, li = lane & 7;
    const int qt   = gridDim.x - 1 - blockIdx.x;   // heavy blocks first
    const int bh   = blockIdx.y;
    const int m0   = wid * 16;

    const __half* Qg = g_Q + ((size_t)bh * SEQ + qt * 128) * DH;
    const __half* Kg = g_K + (size_t)bh * SEQ * DH;
    const __half* Vg = g_V + (size_t)bh * SEQ * DH;

    const uint32_t qaddr0 = sb + ATT_QB
        + (uint32_t)(m0 + (sect & 1) * 8 + li) * 144 + (sect >> 1) * 16;
    const uint32_t koff = (uint32_t)((sect >> 1) * 8 + li) * 144 + (sect & 1) * 16;
    const uint32_t voff = (uint32_t)((sect & 1) * 8 + li) * 144 + (sect >> 1) * 16;

    attn_stage_kv(sb, Kg, Vg, 0, tid);

    // Q scale folds softmax scale AND log2(e): s = log2(exp(q.k/8))
    const __half2 scl = __half2half2(__float2half(0.125f * 1.4426950408889634f));
    #pragma unroll
    for (int i = 0; i < 4; i++) {
        const int p = tid + i * 256;
        const int row = p >> 3, dc = (p & 7) * 8;
        uint4 v = *(const uint4*)(Qg + row * 64 + dc);
        __half2* h = (__half2*)&v;
        h[0] = __hmul2(h[0], scl); h[1] = __hmul2(h[1], scl);
        h[2] = __hmul2(h[2], scl); h[3] = __hmul2(h[3], scl);
        *(uint4*)(smc + ATT_QB + row * 144 + dc * 2) = v;
    }
    __syncthreads();

    uint32_t qa[4][4];
    #pragma unroll
    for (int ks = 0; ks < 4; ks++) ldsm4(qa[ks], qaddr0 + ks * 32);

    float o[8][4];
    #pragma unroll
    for (int nt = 0; nt < 8; nt++)
        #pragma unroll
        for (int i = 0; i < 4; i++) o[nt][i] = 0.f;
    float mrow[2] = {-1e30f, -1e30f};
    float lrow[2] = {0.f, 0.f};

    const int R0  = qt * 128 + m0;
    const int r0g = R0 + g;
    const int r1g = r0g + 8;
    const int ntiles = 2 * qt + 2;

    for (int jt = 0; jt < ntiles; jt++) {
        CP_WAIT(0);
        __syncthreads();
        if (jt + 1 < ntiles) attn_stage_kv(sb, Kg, Vg, jt + 1, tid);

        if (jt * 64 > R0 + 15) continue;

        const int buf = jt & 1;
        const uint32_t kaddr0 = sb + ATT_KB + buf * 9216 + koff;
        const uint32_t vaddr0 = sb + ATT_VB + buf * 9216 + voff;

        float s[8][4];
        #pragma unroll
        for (int nt = 0; nt < 8; nt++)
            #pragma unroll
            for (int i = 0; i < 4; i++) s[nt][i] = 0.f;

        #pragma unroll
        for (int t = 0; t < 4; t++) {
            #pragma unroll
            for (int ks = 0; ks < 4; ks++) {
                uint32_t kb[4];
                ldsm4(kb, kaddr0 + t * 16 * 144 + ks * 32);
                mma_f16(s[2 * t],     qa[ks][0], qa[ks][1], qa[ks][2], qa[ks][3],
                        kb[0], kb[1]);
                mma_f16(s[2 * t + 1], qa[ks][0], qa[ks][1], qa[ks][2], qa[ks][3],
                        kb[2], kb[3]);
            }
        }

        if (jt * 64 + 63 > R0) {
            #pragma unroll
            for (int nt = 0; nt < 8; nt++) {
                const int c = jt * 64 + nt * 8 + 2 * l4;
                if (c     > r0g) s[nt][0] = -1e30f;
                if (c + 1 > r0g) s[nt][1] = -1e30f;
                if (c     > r1g) s[nt][2] = -1e30f;
                if (c + 1 > r1g) s[nt][3] = -1e30f;
            }
        }

        float mx0 = -1e30f, mx1 = -1e30f;
        #pragma unroll
        for (int nt = 0; nt < 8; nt++) {
            mx0 = fmaxf(mx0, fmaxf(s[nt][0], s[nt][1]));
            mx1 = fmaxf(mx1, fmaxf(s[nt][2], s[nt][3]));
        }
        mx0 = fmaxf(mx0, __shfl_xor_sync(0xffffffffu, mx0, 1));
        mx0 = fmaxf(mx0, __shfl_xor_sync(0xffffffffu, mx0, 2));
        mx1 = fmaxf(mx1, __shfl_xor_sync(0xffffffffu, mx1, 1));
        mx1 = fmaxf(mx1, __shfl_xor_sync(0xffffffffu, mx1, 2));

        const float mn0 = fmaxf(mrow[0], mx0);
        const float mn1 = fmaxf(mrow[1], mx1);
        const float c0 = exp2f(mrow[0] - mn0);
        const float c1 = exp2f(mrow[1] - mn1);

        float sum0 = 0.f, sum1 = 0.f;
        #pragma unroll
        for (int nt = 0; nt < 8; nt++) {
            s[nt][0] = exp2f(s[nt][0] - mn0);
            s[nt][1] = exp2f(s[nt][1] - mn0);
            s[nt][2] = exp2f(s[nt][2] - mn1);
            s[nt][3] = exp2f(s[nt][3] - mn1);
            sum0 += s[nt][0] + s[nt][1];
            sum1 += s[nt][2] + s[nt][3];
        }
        sum0 += __shfl_xor_sync(0xffffffffu, sum0, 1);
        sum0 += __shfl_xor_sync(0xffffffffu, sum0, 2);
        sum1 += __shfl_xor_sync(0xffffffffu, sum1, 1);
        sum1 += __shfl_xor_sync(0xffffffffu, sum1, 2);

        lrow[0] = lrow[0] * c0 + sum0;
        lrow[1] = lrow[1] * c1 + sum1;
        mrow[0] = mn0;
        mrow[1] = mn1;
        #pragma unroll
        for (int nt = 0; nt < 8; nt++) {
            o[nt][0] *= c0; o[nt][1] *= c0;
            o[nt][2] *= c1; o[nt][3] *= c1;
        }

        uint32_t ph[4][4];
        #pragma unroll
        for (int ks = 0; ks < 4; ks++) {
            ph[ks][0] = packh2(s[2 * ks][0],     s[2 * ks][1]);
            ph[ks][1] = packh2(s[2 * ks][2],     s[2 * ks][3]);
            ph[ks][2] = packh2(s[2 * ks + 1][0], s[2 * ks + 1][1]);
            ph[ks][3] = packh2(s[2 * ks + 1][2], s[2 * ks + 1][3]);
        }

        #pragma unroll
        for (int t = 0; t < 4; t++) {
            #pragma unroll
            for (int ks = 0; ks < 4; ks++) {
                uint32_t vb[4];
                ldsm4t(vb, vaddr0 + ks * 16 * 144 + t * 32);
                mma_f16(o[2 * t],     ph[ks][0], ph[ks][1], ph[ks][2], ph[ks][3],
                        vb[0], vb[1]);
                mma_f16(o[2 * t + 1], ph[ks][0], ph[ks][1], ph[ks][2], ph[ks][3],
                        vb[2], vb[3]);
            }
        }
    }

    const int b_ = bh >> 4;
    const int h_ = bh & 15;
    const float inv0 = 1.f / lrow[0];
    const float inv1 = 1.f / lrow[1];
    __half* c0p = g_ctx + ((size_t)(b_ * SEQ + qt * 128 + m0 + g))     * DMODEL + h_ * 64;
    __half* c1p = g_ctx + ((size_t)(b_ * SEQ + qt * 128 + m0 + 8 + g)) * DMODEL + h_ * 64;
    #pragma unroll
    for (int nt = 0; nt < 8; nt++) {
        *(uint32_t*)(c0p + nt * 8 + 2 * l4) = packh2(o[nt][0] * inv0, o[nt][1] * inv0);
        *(uint32_t*)(c1p + nt * 8 + 2 * l4) = packh2(o[nt][2] * inv1, o[nt][3] * inv1);
    }
}

// ---------------------------------------------------------------------------
extern "C" void kernel_launch(void* const* d_in, const int* in_sizes, int n_in,
                              void* d_out, int out_size)
{
    const float* x  = (const float*)d_in[0];
    const float* Wq = (const float*)d_in[2];
    const float* bq = (const float*)d_in[3];
    const float* Wk = (const float*)d_in[4];
    const float* bk = (const float*)d_in[5];
    const float* Wv = (const float*)d_in[6];
    const float* bv = (const float*)d_in[7];
    const float* Wo = (const float*)d_in[8];
    const float* bo = (const float*)d_in[9];
    float* out = (float*)d_out;

    __half *qp, *kp, *vp, *cp, *xp, *wqkv, *wo;
    cudaGetSymbolAddress((void**)&xp,   g_X);
    cudaGetSymbolAddress((void**)&wqkv, g_Wqkv);
    cudaGetSymbolAddress((void**)&wo,   g_Wo);
    cudaGetSymbolAddress((void**)&qp,   g_Q);
    cudaGetSymbolAddress((void**)&kp,   g_K);
    cudaGetSymbolAddress((void**)&vp,   g_V);
    cudaGetSymbolAddress((void**)&cp,   g_ctx);

    // Pre-pass: one kernel converts/packs everything
    const int ntot = NX4 + NQKV + NWO;
    conv_all_kernel<<<(ntot + 255) / 256, 256>>>(
        (const float4*)x, (const float4*)Wq, (const float4*)Wk,
        (const float4*)Wv, (const float4*)Wo);

    cudaFuncSetAttribute(gemm_f16_kernel<true>,
                         cudaFuncAttributeMaxDynamicSharedMemorySize, GEMM_SMEM);
    cudaFuncSetAttribute(gemm_f16_kernel<false>,
                         cudaFuncAttributeMaxDynamicSharedMemorySize, GEMM_SMEM);

    // Fused QKV projection: one launch, N = 3072
    gemm_f16_kernel<true><<<dim3(24, 64), 128, GEMM_SMEM>>>(
        xp, wqkv, 3 * DMODEL, bq, bk, bv, qp, kp, vp, nullptr);

    cudaFuncSetAttribute(attn_f16_kernel,
                         cudaFuncAttributeMaxDynamicSharedMemorySize, ATT_SMEM);
    attn_f16_kernel<<<dim3(16, 64), 256, ATT_SMEM>>>();

    // Output projection: N = 1024, fp32 out
    gemm_f16_kernel<false><<<dim3(8, 64), 128, GEMM_SMEM>>>(
        cp, wo, DMODEL, bo, nullptr, nullptr, nullptr, nullptr, nullptr, out);
}